// round 2
// baseline (speedup 1.0000x reference)
#include <cuda_runtime.h>
#include <math.h>

#define B     64
#define T     256
#define U     1024
#define G3    3072
#define NBLK  128     // persistent CTAs, 1 per SM, all co-resident (<=148)
#define NT    256
#define UC    8       // hidden units per CTA (NBLK*UC == U)
#define KC    128     // k-chunk of h staged in smem
#define NCHUNK (U/KC) // 8

// ---- static device scratch (allocation-free rule) ----
__device__ __align__(16) float g_xproj[(size_t)T * B * G3]; // [t][b][3072]
__device__ __align__(16) float g_h[2][B * U];               // double-buffered h, [b][k]
__device__ unsigned g_bar_cnt;
__device__ unsigned g_bar_gen;

typedef unsigned long long ull;

// ---- helpers ----
__device__ __forceinline__ void cpasync16(void* sdst, const void* gsrc) {
    unsigned s = (unsigned)__cvta_generic_to_shared(sdst);
    asm volatile("cp.async.ca.shared.global [%0], [%1], 16;\n" :: "r"(s), "l"(gsrc));
}
__device__ __forceinline__ void cp_commit() { asm volatile("cp.async.commit_group;\n"); }
template<int N> __device__ __forceinline__ void cp_wait() {
    asm volatile("cp.async.wait_group %0;\n" :: "n"(N));
}
// packed fp32x2 FMA: 2 MACs per issue slot (FFMA 3-reg is half-rate on sm_103a)
__device__ __forceinline__ void fma2(ull& acc, ull a, ull b) {
    asm volatile("fma.rn.f32x2 %0, %1, %2, %0;" : "+l"(acc) : "l"(a), "l"(b));
}

// release/acquire centralized grid barrier (all NBLK CTAs co-resident)
__device__ __forceinline__ void grid_barrier() {
    __syncthreads();
    if (threadIdx.x == 0) {
        unsigned gen0;
        asm volatile("ld.acquire.gpu.u32 %0, [%1];" : "=r"(gen0) : "l"(&g_bar_gen));
        unsigned prev;
        asm volatile("atom.release.gpu.global.add.u32 %0, [%1], 1;"
                     : "=r"(prev) : "l"(&g_bar_cnt));
        if (prev == NBLK - 1) {
            asm volatile("st.relaxed.gpu.global.u32 [%0], 0;" :: "l"(&g_bar_cnt));
            asm volatile("red.release.gpu.global.add.u32 [%0], 1;" :: "l"(&g_bar_gen));
        } else {
            unsigned g;
            do {
                asm volatile("ld.acquire.gpu.u32 %0, [%1];" : "=r"(g) : "l"(&g_bar_gen));
            } while (g == gen0);
        }
    }
    __syncthreads();
}

// ---- kernel 1: x_proj[t][b][:] = W_in[x[b][t]][:] + b_in ----
__global__ void gather_k(const int* __restrict__ x,
                         const float* __restrict__ Win,
                         const float* __restrict__ bin) {
    int blk = blockIdx.x;
    int t = blk >> 6;     // 0..255
    int b = blk & 63;     // 0..63
    int v = x[b * T + t];
    const float4* src = (const float4*)(Win + (size_t)v * G3);
    const float4* bi  = (const float4*)bin;
    float4* dst = (float4*)(g_xproj + (size_t)(t * B + b) * G3);
    for (int c = threadIdx.x; c < G3 / 4; c += NT) {
        float4 w = src[c], bb = bi[c];
        w.x += bb.x; w.y += bb.y; w.z += bb.z; w.w += bb.w;
        dst[c] = w;
    }
}

// ---- kernel 2: persistent GRU recurrence ----
// SMEM floats: Ws 24*1028 | hbuf 2*64*132 | xin 64*24 | rec_s 64*25 | brec 24
#define WS_STRIDE 1028
#define HB_STRIDE 132
#define SMEM_FLOATS (24*WS_STRIDE + 2*64*HB_STRIDE + 64*24 + 64*25 + 32)

__global__ void __launch_bounds__(NT, 1)
gru_persist(const float* __restrict__ hidden,
            const float* __restrict__ Wrec,
            const float* __restrict__ brec,
            float* __restrict__ out) {
    extern __shared__ float smem[];
    float* Ws     = smem;                        // [24][1028] col-major-in-k, padded
    float* hbuf   = Ws + 24 * WS_STRIDE;         // 2 x [64][132]
    float* xin    = hbuf + 2 * 64 * HB_STRIDE;   // [64][24]
    float* rec_s  = xin + 64 * 24;               // [64][25]
    float* brec_s = rec_s + 64 * 25;             // [24]

    const int tid = threadIdx.x;
    const int u0  = blockIdx.x * UC;

    // Load the W_rec slice for this CTA's 24 columns (one time)
    for (int idx = tid; idx < 24 * U; idx += NT) {
        int k = idx / 24, j = idx % 24;
        int gate = j >> 3, uu = j & 7;
        Ws[j * WS_STRIDE + k] = Wrec[(size_t)k * G3 + gate * U + u0 + uu];
    }
    if (tid < 24) {
        int gate = tid >> 3, uu = tid & 7;
        brec_s[tid] = brec[gate * U + u0 + uu];
    }
    __syncthreads();

    const int bb = tid >> 2;   // batch 0..63
    const int g  = tid & 3;    // column group: handles j = g*6 .. g*6+5

    for (int t = 0; t < T; t++) {
        const float* hsrc = (t == 0) ? hidden : g_h[t & 1];

        // x_proj gather for this step (24 cols x 64 batches), async
        for (int item = tid; item < 384; item += NT) {
            int b = item / 6, r = item % 6, gate = r >> 1, half = r & 1;
            cpasync16(xin + b * 24 + gate * 8 + half * 4,
                      g_xproj + (size_t)(t * B + b) * G3 + gate * U + u0 + half * 4);
        }
        // h chunk 0
        for (int item = tid; item < 2048; item += NT) {
            int b = item >> 5, s = item & 31;
            cpasync16(hbuf + b * HB_STRIDE + s * 4, hsrc + b * U + s * 4);
        }
        cp_commit();

        ull acc[6];
        #pragma unroll
        for (int jj = 0; jj < 6; jj++) acc[jj] = 0ull;

        for (int c = 0; c < NCHUNK; c++) {
            if (c + 1 < NCHUNK) {
                float* dbuf = hbuf + ((c + 1) & 1) * (64 * HB_STRIDE);
                const float* src = hsrc + (c + 1) * KC;
                for (int item = tid; item < 2048; item += NT) {
                    int b = item >> 5, s = item & 31;
                    cpasync16(dbuf + b * HB_STRIDE + s * 4, src + b * U + s * 4);
                }
                cp_commit();
                cp_wait<1>();
            } else {
                cp_wait<0>();
            }
            __syncthreads();

            const ull* hp = (const ull*)(hbuf + (c & 1) * (64 * HB_STRIDE) + bb * HB_STRIDE);
            const ull* wp = (const ull*)(Ws + (g * 6) * WS_STRIDE + c * KC);
            #pragma unroll 4
            for (int k4 = 0; k4 < KC / 4; k4++) {
                ull h01 = hp[k4 * 2], h23 = hp[k4 * 2 + 1];
                #pragma unroll
                for (int jj = 0; jj < 6; jj++) {
                    ull w01 = wp[jj * (WS_STRIDE / 2) + k4 * 2];
                    ull w23 = wp[jj * (WS_STRIDE / 2) + k4 * 2 + 1];
                    fma2(acc[jj], h01, w01);
                    fma2(acc[jj], h23, w23);
                }
            }
            __syncthreads();
        }

        // finalize rec = acc.x + acc.y + b_rec
        #pragma unroll
        for (int jj = 0; jj < 6; jj++) {
            float2 f = *(float2*)&acc[jj];
            rec_s[bb * 25 + g * 6 + jj] = f.x + f.y + brec_s[g * 6 + jj];
        }
        __syncthreads();

        // gates + state update + outputs
        #pragma unroll
        for (int i = 0; i < 2; i++) {
            int item = tid + i * NT;
            int b = item >> 3, uu = item & 7;
            float xz = xin[b * 24 + uu];
            float xr = xin[b * 24 + 8 + uu];
            float xh = xin[b * 24 + 16 + uu];
            float rz = rec_s[b * 25 + uu];
            float rr = rec_s[b * 25 + 8 + uu];
            float rh = rec_s[b * 25 + 16 + uu];
            float z  = 1.f / (1.f + expf(-(xz + rz)));
            float r  = 1.f / (1.f + expf(-(xr + rr)));
            float hh = tanhf(xh + r * rh);
            float hold = hsrc[b * U + u0 + uu];
            float hn = z * hold + (1.f - z) * hh;
            out[((size_t)b * T + t) * U + u0 + uu] = hn;
            g_h[(t + 1) & 1][b * U + u0 + uu] = hn;
            if (t == T - 1)
                out[(size_t)B * T * U + (size_t)b * U + u0 + uu] = hn;
        }
        grid_barrier();
    }
}

extern "C" void kernel_launch(void* const* d_in, const int* in_sizes, int n_in,
                              void* d_out, int out_size) {
    const int*   x      = (const int*)d_in[0];
    const float* hidden = (const float*)d_in[1];
    const float* Win    = (const float*)d_in[2];
    const float* Wrec   = (const float*)d_in[3];
    const float* bin    = (const float*)d_in[4];
    const float* brec   = (const float*)d_in[5];
    float* out = (float*)d_out;

    gather_k<<<T * B, NT>>>(x, Win, bin);

    size_t smem_bytes = SMEM_FLOATS * sizeof(float);
    cudaFuncSetAttribute(gru_persist, cudaFuncAttributeMaxDynamicSharedMemorySize,
                         (int)smem_bytes);
    gru_persist<<<NBLK, NT, smem_bytes>>>(hidden, Wrec, brec, out);
}

// round 4
// speedup vs baseline: 3.4383x; 3.4383x over previous
#include <cuda_runtime.h>
#include <cuda_bf16.h>
#include <cstdint>
#include <math.h>

#define B     64
#define T     256
#define U     1024
#define G3    3072
#define NBLK  128
#define NT    256

// ---- static device scratch ----
__device__ __align__(16) float g_xproj[(size_t)T * B * G3];   // [t][b][3072]
// combined h buffer: rows 0-63 = h_hi[b], rows 64-127 = h_lo[b]; double-buffered
__device__ __align__(16) __nv_bfloat16 g_hb[2][128 * U];
__device__ unsigned g_bar_cnt;
__device__ unsigned g_bar_gen;

// ---- SMEM layout (bytes) ----
// W: [2 pass][24 n][1032 k] bf16 ; n-stride 2064B, pass-stride 49536B
#define SM_W     0
#define W_NSTR   2064
#define W_PSTR   49536
// A: [2 buf][128 rows][136 cols] bf16 ; row-stride 272B, buf-stride 34816B
#define SM_A     99328
#define A_RSTR   272
#define A_BSTR   34816
#define SM_REC   168960   // float [64][26]
#define SM_XIN   175680   // float [64][28]
#define SM_BREC  182848   // float [24]
#define SMEM_TOTAL 183040

// ---- PTX helpers ----
__device__ __forceinline__ uint32_t smem_u32(const void* p) {
    uint32_t a;
    asm("{ .reg .u64 t; cvta.to.shared.u64 t, %1; cvt.u32.u64 %0, t; }" : "=r"(a) : "l"(p));
    return a;
}
__device__ __forceinline__ void cpasync16(uint32_t sdst, const void* gsrc) {
    asm volatile("cp.async.ca.shared.global [%0], [%1], 16;\n" :: "r"(sdst), "l"(gsrc));
}
__device__ __forceinline__ void cp_commit() { asm volatile("cp.async.commit_group;\n"); }
template<int N> __device__ __forceinline__ void cp_wait() {
    asm volatile("cp.async.wait_group %0;\n" :: "n"(N));
}
__device__ __forceinline__ void ldsm4(uint32_t* r, uint32_t addr) {
    asm volatile("ldmatrix.sync.aligned.m8n8.x4.shared.b16 {%0,%1,%2,%3}, [%4];"
                 : "=r"(r[0]), "=r"(r[1]), "=r"(r[2]), "=r"(r[3]) : "r"(addr));
}
__device__ __forceinline__ void ldsm2(uint32_t* r, uint32_t addr) {
    asm volatile("ldmatrix.sync.aligned.m8n8.x2.shared.b16 {%0,%1}, [%2];"
                 : "=r"(r[0]), "=r"(r[1]) : "r"(addr));
}
__device__ __forceinline__ void mma_bf16(float* c, const uint32_t* a, uint32_t b0, uint32_t b1) {
    asm volatile("mma.sync.aligned.m16n8k16.row.col.f32.bf16.bf16.f32 "
                 "{%0,%1,%2,%3}, {%4,%5,%6,%7}, {%8,%9}, {%0,%1,%2,%3};"
                 : "+f"(c[0]), "+f"(c[1]), "+f"(c[2]), "+f"(c[3])
                 : "r"(a[0]), "r"(a[1]), "r"(a[2]), "r"(a[3]), "r"(b0), "r"(b1));
}

// ---- grid barrier (all NBLK CTAs co-resident) ----
__device__ __forceinline__ void grid_barrier() {
    __syncthreads();
    if (threadIdx.x == 0) {
        unsigned gen0;
        asm volatile("ld.acquire.gpu.u32 %0, [%1];" : "=r"(gen0) : "l"(&g_bar_gen));
        unsigned prev;
        asm volatile("atom.release.gpu.global.add.u32 %0, [%1], 1;" : "=r"(prev) : "l"(&g_bar_cnt));
        if (prev == NBLK - 1) {
            asm volatile("st.relaxed.gpu.global.u32 [%0], 0;" :: "l"(&g_bar_cnt));
            asm volatile("red.release.gpu.global.add.u32 [%0], 1;" :: "l"(&g_bar_gen));
        } else {
            unsigned g;
            do { asm volatile("ld.acquire.gpu.u32 %0, [%1];" : "=r"(g) : "l"(&g_bar_gen)); } while (g == gen0);
        }
    }
    __syncthreads();
}

// ---- kernel 1: x_proj = W_in[x] + b_in ----
__global__ void gather_k(const int* __restrict__ x, const float* __restrict__ Win,
                         const float* __restrict__ bin) {
    int blk = blockIdx.x;
    int t = blk >> 6, b = blk & 63;
    int v = x[b * T + t];
    const float4* src = (const float4*)(Win + (size_t)v * G3);
    const float4* bi  = (const float4*)bin;
    float4* dst = (float4*)(g_xproj + (size_t)(t * B + b) * G3);
    for (int c = threadIdx.x; c < G3 / 4; c += NT) {
        float4 w = src[c], bb = bi[c];
        w.x += bb.x; w.y += bb.y; w.z += bb.z; w.w += bb.w;
        dst[c] = w;
    }
}

// producer staging of one K=128 chunk of A (128 rows x 128 cols bf16)
__device__ __forceinline__ void stage_chunk(uint32_t sbase, int buf, int kofs,
                                            const __nv_bfloat16* hb, int ptid) {
    uint32_t dstbase = sbase + SM_A + buf * A_BSTR;
    #pragma unroll
    for (int i = 0; i < 16; i++) {
        int it = ptid + i * 128;
        int row = it >> 4, g8 = it & 15;
        cpasync16(dstbase + row * A_RSTR + g8 * 16, hb + row * U + kofs + g8 * 8);
    }
}

// ---- kernel 2: persistent HMMA-split GRU ----
__global__ void __launch_bounds__(NT, 1)
gru_mma(const float* __restrict__ hidden, const float* __restrict__ Wrec,
        const float* __restrict__ brec, float* __restrict__ out) {
    extern __shared__ __align__(1024) char smem[];
    const uint32_t sbase = smem_u32(smem);
    const int tid = threadIdx.x;
    const int wid = tid >> 5;
    const int l   = tid & 31;
    const int u0  = blockIdx.x * 8;

    float* rec_s  = (float*)(smem + SM_REC);
    float* xin_s  = (float*)(smem + SM_XIN);
    float* brec_s = (float*)(smem + SM_BREC);

    // ---- one-time: W_rec slice -> bf16 hi/lo, [pass][n][k] ----
    for (int idx = tid; idx < 24 * U; idx += NT) {
        int k = idx >> 5 | 0;  // placeholder avoided; compute below
        k = idx / 24;
        int j = idx - k * 24;
        int gate = j >> 3, uu = j & 7;
        float w = Wrec[(size_t)k * G3 + gate * U + u0 + uu];
        __nv_bfloat16 hi = __float2bfloat16(w);
        __nv_bfloat16 lo = __float2bfloat16(w - __bfloat162float(hi));
        *(__nv_bfloat16*)(smem + SM_W + j * W_NSTR + k * 2) = hi;
        *(__nv_bfloat16*)(smem + SM_W + W_PSTR + j * W_NSTR + k * 2) = lo;
    }
    if (tid < 24) {
        int gate = tid >> 3, uu = tid & 7;
        brec_s[tid] = brec[gate * U + u0 + uu];
    }

    // ---- init h_old registers + global bf16 h buffer 0 ----
    float hold[2];
    #pragma unroll
    for (int i = 0; i < 2; i++) {
        int item = tid + i * NT;
        int b = item >> 3, uu = item & 7;
        float h0 = hidden[b * U + u0 + uu];
        hold[i] = h0;
        __nv_bfloat16 hi = __float2bfloat16(h0);
        g_hb[0][b * U + u0 + uu] = hi;
        g_hb[0][(64 + b) * U + u0 + uu] = __float2bfloat16(h0 - __bfloat162float(hi));
    }
    grid_barrier();

    // lane-dependent ldmatrix address offsets (byte offsets)
    const uint32_t aoff_hi = (uint32_t)(16 * wid + (l & 15)) * A_RSTR + (l >> 4) * 16;
    const uint32_t aoff_lo = aoff_hi + 64 * A_RSTR;
    const uint32_t boff    = (uint32_t)(l & 7) * W_NSTR + (l & 8) * 2;

    for (int t = 0; t < T; t++) {
        const int par = t & 1;
        const __nv_bfloat16* hb = g_hb[par];

        if (tid >= 128) {
            int ptid = tid - 128;
            // x_proj slice (24 cols x 64 batches) : 384 x 16B
            #pragma unroll
            for (int i = 0; i < 3; i++) {
                int it = ptid + i * 128;
                int b = it / 6, r = it - b * 6;
                int gate = r >> 1, half = r & 1;
                cpasync16(sbase + SM_XIN + (uint32_t)(b * 28 + gate * 8 + half * 4) * 4,
                          g_xproj + ((size_t)t * B + b) * G3 + gate * U + u0 + half * 4);
            }
            stage_chunk(sbase, 0, 0, hb, ptid);
            cp_commit();
        }

        float acc[3][3][4];
        #pragma unroll
        for (int q = 0; q < 3; q++)
            #pragma unroll
            for (int n = 0; n < 3; n++)
                #pragma unroll
                for (int e = 0; e < 4; e++) acc[q][n][e] = 0.f;

        for (int c = 0; c < 8; c++) {
            if (tid >= 128) {
                if (c < 7) {
                    stage_chunk(sbase, (c + 1) & 1, (c + 1) * 128, hb, tid - 128);
                    cp_commit();
                    cp_wait<1>();
                } else {
                    cp_wait<0>();
                }
            }
            __syncthreads();

            if (wid < 4) {
                uint32_t abase = sbase + SM_A + (c & 1) * A_BSTR;
                #pragma unroll
                for (int kk = 0; kk < 8; kk++) {
                    uint32_t r0[4], r1[4];
                    ldsm4(r0, abase + aoff_hi + kk * 32);
                    ldsm4(r1, abase + aoff_lo + kk * 32);
                    uint32_t kgb = (uint32_t)(c * 128 + kk * 16) * 2;
                    #pragma unroll
                    for (int nt = 0; nt < 3; nt++) {
                        uint32_t bh[2], bl[2];
                        uint32_t bb = sbase + SM_W + nt * 8 * W_NSTR + boff + kgb;
                        ldsm2(bh, bb);
                        ldsm2(bl, bb + W_PSTR);
                        mma_bf16(acc[0][nt], r0, bh[0], bh[1]);   // h_hi @ W_hi
                        mma_bf16(acc[1][nt], r0, bl[0], bl[1]);   // h_hi @ W_lo
                        mma_bf16(acc[2][nt], r1, bh[0], bh[1]);   // h_lo @ W_hi
                    }
                }
            }
            __syncthreads();
        }

        // ---- epilogue: combine three tiles -> rec_s[64][26] ----
        if (wid < 4) {
            int row = l >> 2, c2 = (l & 3) * 2;
            int b0r = 16 * wid + row;
            #pragma unroll
            for (int nt = 0; nt < 3; nt++) {
                float s0 = acc[0][nt][0] + acc[1][nt][0] + acc[2][nt][0];
                float s1 = acc[0][nt][1] + acc[1][nt][1] + acc[2][nt][1];
                float s2 = acc[0][nt][2] + acc[1][nt][2] + acc[2][nt][2];
                float s3 = acc[0][nt][3] + acc[1][nt][3] + acc[2][nt][3];
                rec_s[b0r * 26 + nt * 8 + c2]     = s0;
                rec_s[b0r * 26 + nt * 8 + c2 + 1] = s1;
                rec_s[(b0r + 8) * 26 + nt * 8 + c2]     = s2;
                rec_s[(b0r + 8) * 26 + nt * 8 + c2 + 1] = s3;
            }
        }
        __syncthreads();

        // ---- gates + state update + outputs ----
        #pragma unroll
        for (int i = 0; i < 2; i++) {
            int item = tid + i * NT;
            int b = item >> 3, uu = item & 7;
            float rz = rec_s[b * 26 + uu]      + brec_s[uu];
            float rr = rec_s[b * 26 + 8 + uu]  + brec_s[8 + uu];
            float rh = rec_s[b * 26 + 16 + uu] + brec_s[16 + uu];
            float xz = xin_s[b * 28 + uu];
            float xr = xin_s[b * 28 + 8 + uu];
            float xh = xin_s[b * 28 + 16 + uu];
            float z  = 1.f / (1.f + expf(-(xz + rz)));
            float r  = 1.f / (1.f + expf(-(xr + rr)));
            float hh = tanhf(xh + r * rh);
            float hn = z * hold[i] + (1.f - z) * hh;
            hold[i] = hn;
            out[((size_t)b * T + t) * U + u0 + uu] = hn;
            __nv_bfloat16 nh = __float2bfloat16(hn);
            g_hb[par ^ 1][b * U + u0 + uu] = nh;
            g_hb[par ^ 1][(64 + b) * U + u0 + uu] = __float2bfloat16(hn - __bfloat162float(nh));
            if (t == T - 1)
                out[(size_t)B * T * U + (size_t)b * U + u0 + uu] = hn;
        }
        grid_barrier();
    }
}

extern "C" void kernel_launch(void* const* d_in, const int* in_sizes, int n_in,
                              void* d_out, int out_size) {
    const int*   x      = (const int*)d_in[0];
    const float* hidden = (const float*)d_in[1];
    const float* Win    = (const float*)d_in[2];
    const float* Wrec   = (const float*)d_in[3];
    const float* bin    = (const float*)d_in[4];
    const float* brec   = (const float*)d_in[5];
    float* out = (float*)d_out;

    gather_k<<<T * B, NT>>>(x, Win, bin);

    cudaFuncSetAttribute(gru_mma, cudaFuncAttributeMaxDynamicSharedMemorySize, SMEM_TOTAL);
    gru_mma<<<NBLK, NT, SMEM_TOTAL>>>(hidden, Wrec, brec, out);
}

// round 5
// speedup vs baseline: 4.8070x; 1.3981x over previous
#include <cuda_runtime.h>
#include <cuda_bf16.h>
#include <cstdint>
#include <math.h>

#define B     64
#define T     256
#define U     1024
#define G3    3072
#define NBLK  128
#define NT    256

// ---- static device scratch ----
// h packed in MMA A-fragment order:
// [par][ (bt*64 + kk)*2 + half ][ lane ] -> uint4 = {a0,a1,a2,a3}
//   bt = batch-tile (16 batches), kk = k-tile (16 k), half: 0=hi,1=lo
__device__ __align__(16) uint4 g_hpk[2][4 * 64 * 2 * 32];
__device__ unsigned g_bar_cnt;
__device__ unsigned g_bar_gen;

// ---- SMEM layout (bytes) ----
// W: [2 pass][24 n][1032 k] bf16
#define SM_W     0
#define W_NSTR   2064
#define W_PSTR   49536
#define SM_REC   99072               // float [2 plane][64][26]
#define REC_PF   1664                // floats per plane
#define SMEM_TOTAL (99072 + 2*6656)  // 112384

// ---- PTX helpers ----
__device__ __forceinline__ uint32_t smem_u32(const void* p) {
    uint32_t a;
    asm("{ .reg .u64 t; cvta.to.shared.u64 t, %1; cvt.u32.u64 %0, t; }" : "=r"(a) : "l"(p));
    return a;
}
__device__ __forceinline__ void ldsm2(uint32_t* r, uint32_t addr) {
    asm volatile("ldmatrix.sync.aligned.m8n8.x2.shared.b16 {%0,%1}, [%2];"
                 : "=r"(r[0]), "=r"(r[1]) : "r"(addr));
}
__device__ __forceinline__ void mma4(float* c, const uint4& a, uint32_t b0, uint32_t b1) {
    asm volatile("mma.sync.aligned.m16n8k16.row.col.f32.bf16.bf16.f32 "
                 "{%0,%1,%2,%3}, {%4,%5,%6,%7}, {%8,%9}, {%0,%1,%2,%3};"
                 : "+f"(c[0]), "+f"(c[1]), "+f"(c[2]), "+f"(c[3])
                 : "r"(a.x), "r"(a.y), "r"(a.z), "r"(a.w), "r"(b0), "r"(b1));
}

// ---- grid barrier (all NBLK CTAs co-resident) ----
__device__ __forceinline__ void grid_barrier() {
    __syncthreads();
    if (threadIdx.x == 0) {
        unsigned gen0;
        asm volatile("ld.acquire.gpu.u32 %0, [%1];" : "=r"(gen0) : "l"(&g_bar_gen));
        unsigned prev;
        asm volatile("atom.release.gpu.global.add.u32 %0, [%1], 1;" : "=r"(prev) : "l"(&g_bar_cnt));
        if (prev == NBLK - 1) {
            asm volatile("st.relaxed.gpu.global.u32 [%0], 0;" :: "l"(&g_bar_cnt));
            asm volatile("red.release.gpu.global.add.u32 [%0], 1;" :: "l"(&g_bar_gen));
        } else {
            unsigned g;
            do { asm volatile("ld.acquire.gpu.u32 %0, [%1];" : "=r"(g) : "l"(&g_bar_gen)); } while (g == gen0);
        }
    }
    __syncthreads();
}

// pack a thread's (b, uu0..uu0+1) h values (hi+lo bf16 pairs) into g_hpk[buf]
__device__ __forceinline__ void pack_h(int buf, int b, int up, int u0, float2 hn) {
    __nv_bfloat16 h0 = __float2bfloat16(hn.x);
    __nv_bfloat16 h1 = __float2bfloat16(hn.y);
    __nv_bfloat16 l0 = __float2bfloat16(hn.x - __bfloat162float(h0));
    __nv_bfloat16 l1 = __float2bfloat16(hn.y - __bfloat162float(h1));
    uint32_t hip = (uint32_t)__bfloat16_as_ushort(h0) | ((uint32_t)__bfloat16_as_ushort(h1) << 16);
    uint32_t lop = (uint32_t)__bfloat16_as_ushort(l0) | ((uint32_t)__bfloat16_as_ushort(l1) << 16);
    int bt = b >> 4, kk = u0 >> 4;
    int r  = b & 15;
    int lane = (r & 7) * 4 + up;
    int reg  = ((r >> 3) & 1) + (((u0 >> 3) & 1) << 1);
    uint32_t* dst = (uint32_t*)(g_hpk[buf] + (size_t)((bt * 64 + kk) * 2) * 32 + lane) + reg;
    *dst = hip;           // hi half-block
    *(dst + 128) = lop;   // lo half-block (+512B)
}

__device__ __forceinline__ float2 sigm2(float2 a) {
    float2 r; r.x = 1.f / (1.f + expf(-a.x)); r.y = 1.f / (1.f + expf(-a.y)); return r;
}

// ---- persistent HMMA-split GRU, fragment-packed h exchange ----
__global__ void __launch_bounds__(NT, 1)
gru_all(const int* __restrict__ x, const float* __restrict__ hidden,
        const float* __restrict__ Win, const float* __restrict__ Wrec,
        const float* __restrict__ bin, const float* __restrict__ brec,
        float* __restrict__ out) {
    extern __shared__ __align__(1024) char smem[];
    const uint32_t sbase = smem_u32(smem);
    float* rec_s = (float*)(smem + SM_REC);
    const int tid = threadIdx.x;
    const int wid = tid >> 5;
    const int l   = tid & 31;
    const int u0  = blockIdx.x * 8;

    // ---- one-time: W_rec slice -> bf16 hi/lo in SMEM [pass][n][k] ----
    for (int idx = tid; idx < 24 * U; idx += NT) {
        int k = idx / 24;
        int j = idx - k * 24;
        int gate = j >> 3, uu = j & 7;
        float w = Wrec[(size_t)k * G3 + gate * U + u0 + uu];
        __nv_bfloat16 hi = __float2bfloat16(w);
        __nv_bfloat16 lo = __float2bfloat16(w - __bfloat162float(hi));
        *(__nv_bfloat16*)(smem + SM_W + j * W_NSTR + k * 2) = hi;
        *(__nv_bfloat16*)(smem + SM_W + W_PSTR + j * W_NSTR + k * 2) = lo;
    }

    // ---- per-thread gate mapping: (b, uu0=2*up, uu0+1) ----
    const int b  = tid >> 2;
    const int up = tid & 3;
    const int uu0 = up * 2;

    float2 bi[3], br[3];
    #pragma unroll
    for (int g = 0; g < 3; g++) {
        bi[g] = *(const float2*)&bin[g * U + u0 + uu0];
        br[g] = *(const float2*)&brec[g * U + u0 + uu0];
    }
    float2 hold = *(const float2*)&hidden[b * U + u0 + uu0];
    pack_h(0, b, up, u0, hold);
    int tok = x[b * T + 0];
    grid_barrier();

    // ---- warp MMA mapping ----
    const int bt = wid & 3;           // batch tile (16 batches)
    const int kh = wid >> 2;          // k half (32 k-tiles)
    const uint32_t boff = (uint32_t)(l & 7) * W_NSTR + (l & 8) * 2;
    const int blk0 = (bt * 64 + kh * 32) * 2;

    for (int t = 0; t < T; t++) {
        const int par = t & 1;

        // gate-input loads (latency hidden behind GEMM)
        float2 xw0 = *(const float2*)&Win[(size_t)tok * G3 + 0 * U + u0 + uu0];
        float2 xw1 = *(const float2*)&Win[(size_t)tok * G3 + 1 * U + u0 + uu0];
        float2 xw2 = *(const float2*)&Win[(size_t)tok * G3 + 2 * U + u0 + uu0];
        int tok_n = (t + 1 < T) ? x[b * T + t + 1] : 0;

        // ---- GEMM: 32 k-tiles, distance-2 prefetched A frags from L2 ----
        const uint4* base = g_hpk[par] + (size_t)blk0 * 32 + l;
        float acc[3][4];
        #pragma unroll
        for (int nt = 0; nt < 3; nt++)
            #pragma unroll
            for (int e = 0; e < 4; e++) acc[nt][e] = 0.f;

        uint4 Ah[2], Al[2];
        Ah[0] = __ldcg(base);       Al[0] = __ldcg(base + 32);
        Ah[1] = __ldcg(base + 64);  Al[1] = __ldcg(base + 96);

        #pragma unroll
        for (int kkl = 0; kkl < 32; kkl++) {
            uint4 ch = Ah[kkl & 1], cl = Al[kkl & 1];
            if (kkl < 30) {
                const uint4* p = base + (kkl + 2) * 64;
                Ah[kkl & 1] = __ldcg(p);
                Al[kkl & 1] = __ldcg(p + 32);
            }
            uint32_t kgb = (uint32_t)(kh * 32 + kkl) * 32;
            #pragma unroll
            for (int nt = 0; nt < 3; nt++) {
                uint32_t bb = sbase + SM_W + nt * 8 * W_NSTR + boff + kgb;
                uint32_t bh[2], bl[2];
                ldsm2(bh, bb);
                ldsm2(bl, bb + W_PSTR);
                mma4(acc[nt], ch, bh[0], bh[1]);   // h_hi @ W_hi
                mma4(acc[nt], ch, bl[0], bl[1]);   // h_hi @ W_lo
                mma4(acc[nt], cl, bh[0], bh[1]);   // h_lo @ W_hi
            }
        }

        // ---- epilogue: write this warp's rec partials to its plane ----
        {
            int bb0 = bt * 16 + (l >> 2);
            float* pl = rec_s + kh * REC_PF;
            #pragma unroll
            for (int nt = 0; nt < 3; nt++) {
                int j0 = nt * 8 + (l & 3) * 2;
                *(float2*)&pl[bb0 * 26 + j0]       = make_float2(acc[nt][0], acc[nt][1]);
                *(float2*)&pl[(bb0 + 8) * 26 + j0] = make_float2(acc[nt][2], acc[nt][3]);
            }
        }
        __syncthreads();

        // ---- gates: 2 units per thread ----
        {
            float2 r0a = *(float2*)&rec_s[b * 26 + 0 + uu0];
            float2 r1a = *(float2*)&rec_s[b * 26 + 8 + uu0];
            float2 r2a = *(float2*)&rec_s[b * 26 + 16 + uu0];
            float2 r0b = *(float2*)&rec_s[REC_PF + b * 26 + 0 + uu0];
            float2 r1b = *(float2*)&rec_s[REC_PF + b * 26 + 8 + uu0];
            float2 r2b = *(float2*)&rec_s[REC_PF + b * 26 + 16 + uu0];

            float2 az, ar, ah;
            az.x = xw0.x + bi[0].x + r0a.x + r0b.x + br[0].x;
            az.y = xw0.y + bi[0].y + r0a.y + r0b.y + br[0].y;
            ar.x = xw1.x + bi[1].x + r1a.x + r1b.x + br[1].x;
            ar.y = xw1.y + bi[1].y + r1a.y + r1b.y + br[1].y;
            ah.x = xw2.x + bi[2].x;
            ah.y = xw2.y + bi[2].y;
            float rhx = r2a.x + r2b.x + br[2].x;
            float rhy = r2a.y + r2b.y + br[2].y;

            float2 z = sigm2(az);
            float2 r = sigm2(ar);
            float2 hh;
            hh.x = tanhf(ah.x + r.x * rhx);
            hh.y = tanhf(ah.y + r.y * rhy);
            float2 hn;
            hn.x = z.x * hold.x + (1.f - z.x) * hh.x;
            hn.y = z.y * hold.y + (1.f - z.y) * hh.y;
            hold = hn;

            *(float2*)&out[((size_t)b * T + t) * U + u0 + uu0] = hn;
            if (t == T - 1)
                *(float2*)&out[(size_t)B * T * U + (size_t)b * U + u0 + uu0] = hn;
            pack_h(par ^ 1, b, up, u0, hn);
        }
        tok = tok_n;
        grid_barrier();
    }
}

extern "C" void kernel_launch(void* const* d_in, const int* in_sizes, int n_in,
                              void* d_out, int out_size) {
    const int*   x      = (const int*)d_in[0];
    const float* hidden = (const float*)d_in[1];
    const float* Win    = (const float*)d_in[2];
    const float* Wrec   = (const float*)d_in[3];
    const float* bin    = (const float*)d_in[4];
    const float* brec   = (const float*)d_in[5];
    float* out = (float*)d_out;

    cudaFuncSetAttribute(gru_all, cudaFuncAttributeMaxDynamicSharedMemorySize, SMEM_TOTAL);
    gru_all<<<NBLK, NT, SMEM_TOTAL>>>(x, hidden, Win, Wrec, bin, brec, out);
}